// round 14
// baseline (speedup 1.0000x reference)
#include <cuda_runtime.h>
#include <cuda_fp16.h>
#include <cstdint>

#define NN 50000
#define NE 800000
#define SCAN_B 512
#define SCAN_NB ((NN + SCAN_B - 1) / SCAN_B)  // 98
#define EB ((NE + 255) / 256)                 // 3125 fill blocks

// ---------------------------------------------------------------------------
// Scratch (__device__ globals). g_degcnt zero at load, restored by k_scan1.
// Symbols referenced ONLY from device code (R12 lesson).
// ---------------------------------------------------------------------------
__device__ unsigned long long g_degcnt[NN];
__device__ float              g_dinv[NN];
__device__ int                g_off[NN + 1];
__device__ int                g_cursor[NN];
__device__ int                g_bsum[SCAN_NB];
__device__ __align__(8) uint2 g_edge[NE];        // (src, coef bits), sorted by dest
__device__ __align__(16) __half2 g_mA[NN * 64];  // message ping
__device__ __align__(16) __half2 g_mB[NN * 64];  // message pong

// ---------------------------------------------------------------------------
__device__ __forceinline__ void mma_f16(float4& d, uint32_t a0, uint32_t a1,
                                        uint32_t a2, uint32_t a3,
                                        uint32_t b0, uint32_t b1) {
    asm volatile(
        "mma.sync.aligned.m16n8k16.row.col.f32.f16.f16.f32 "
        "{%0,%1,%2,%3}, {%4,%5,%6,%7}, {%8,%9}, {%0,%1,%2,%3};"
        : "+f"(d.x), "+f"(d.y), "+f"(d.z), "+f"(d.w)
        : "r"(a0), "r"(a1), "r"(a2), "r"(a3), "r"(b0), "r"(b1));
}

__device__ __forceinline__ int detect_is64(const int* __restrict__ ei32) {
    __shared__ int nz;
    if (threadIdx.x == 0) nz = 0;
    __syncthreads();
    for (int k = threadIdx.x; k < 512; k += blockDim.x)
        if (ei32[2 * k + 1] != 0) nz = 1;
    __syncthreads();
    return nz == 0;
}

__device__ __forceinline__ int load_idx(const void* ei, long i, int is64) {
    int v = is64 ? (int)((const long long*)ei)[i] : ((const int*)ei)[i];
    return min(max(v, 0), NN - 1);
}

// ---------------------------------------------------------------------------
// Preprocess
// ---------------------------------------------------------------------------
__global__ void k_deg_count(const void* __restrict__ ei, const float* __restrict__ ew) {
    int is64 = detect_is64((const int*)ei);
    int e = blockIdx.x * blockDim.x + threadIdx.x;
    if (e < NE) {
        int col = load_idx(ei, (long)NE + e, is64);
        unsigned long long v =
            (1ull << 40) | (unsigned long long)(ew[e] * 4294967296.0f);
        atomicAdd(&g_degcnt[col], v);
    }
}

__global__ void k_scan1() {
    __shared__ int s[SCAN_B];
    int tid = threadIdx.x;
    int i = blockIdx.x * SCAN_B + tid;
    int v = 0;
    if (i < NN) {
        unsigned long long dc = g_degcnt[i];
        g_degcnt[i] = 0ull;  // restore invariant
        float deg = (float)(dc & 0xFFFFFFFFFFull) * 2.3283064365386963e-10f;
        g_dinv[i] = rsqrtf(deg + 1.0f);
        v = (int)(dc >> 40);
    }
    s[tid] = v;
    __syncthreads();
#pragma unroll
    for (int off = 1; off < SCAN_B; off <<= 1) {
        int t = (tid >= off) ? s[tid - off] : 0;
        __syncthreads();
        s[tid] += t;
        __syncthreads();
    }
    if (i < NN) g_off[i] = s[tid] - v;
    if (tid == SCAN_B - 1) g_bsum[blockIdx.x] = s[tid];
}

__global__ void k_scan23() {
    __shared__ int s[128];
    __shared__ int pre[SCAN_NB];
    int tid = threadIdx.x;
    int v = 0;
    if (tid < 128) { v = (tid < SCAN_NB) ? g_bsum[tid] : 0; s[tid] = v; }
    __syncthreads();
#pragma unroll
    for (int off = 1; off < 128; off <<= 1) {
        int t = 0;
        if (tid < 128 && tid >= off) t = s[tid - off];
        __syncthreads();
        if (tid < 128) s[tid] += t;
        __syncthreads();
    }
    if (tid < SCAN_NB) pre[tid] = s[tid] - v;
    __syncthreads();
    int i = blockIdx.x * blockDim.x + tid;
    if (i < NN) {
        int o = g_off[i] + pre[i / SCAN_B];
        g_off[i] = o;
        g_cursor[i] = o;
    }
    if (i == 0) g_off[NN] = NE;
}

// ---------------------------------------------------------------------------
// Combined fill + gemm1. Blocks [0,EB) build the CSR edge array; blocks
// [EB,EB+782) compute mA = x @ W1^T. Provably independent: fill reads
// ei/ew/g_dinv writes g_edge; gemm1 reads x/W1 writes g_mA. The fill blocks'
// L2-bound scatter hides under gemm1's tensor work.
// ---------------------------------------------------------------------------
__device__ void fill_body(const void* __restrict__ ei, const float* __restrict__ ew) {
    int is64 = detect_is64((const int*)ei);
    int e = blockIdx.x * blockDim.x + threadIdx.x;
    if (e < NE) {
        int row = load_idx(ei, e, is64);
        int col = load_idx(ei, (long)NE + e, is64);
        int pos = atomicAdd(&g_cursor[col], 1);
        pos = min(max(pos, 0), NE - 1);
        float coef = g_dinv[row] * ew[e] * g_dinv[col];
        uint2 rec;
        rec.x = (uint32_t)row;
        rec.y = __float_as_uint(coef);
        g_edge[pos] = rec;
    }
}

__device__ void gemm1_body(const float* __restrict__ x, const float* __restrict__ W) {
    constexpr int D = 128, NT = D / 32;
    __shared__ __half2 Wh[D * 20];
    __shared__ __half2 hs2[64 * 20];

    const int tid = threadIdx.x;
    const int warp = tid >> 5, lane = tid & 31;
    const int wm = warp >> 2, wn = warp & 3;
    const int gid = lane >> 2, tig = lane & 3;
    const int row0 = (blockIdx.x - EB) * 64;

    float4 acc[2][NT];
#pragma unroll
    for (int s = 0; s < 2; s++)
#pragma unroll
        for (int t = 0; t < NT; t++) acc[s][t] = make_float4(0.f, 0.f, 0.f, 0.f);

    for (int c = 0; c < 4; c++) {
        for (int idx = tid; idx < D * 16; idx += 256) {
            int n = idx >> 4, kk = idx & 15;
            float2 wv = *(const float2*)(W + n * 128 + c * 32 + kk * 2);
            Wh[n * 20 + kk] = __floats2half2_rn(wv.x, wv.y);
        }
        for (int idx = tid; idx < 512; idx += 256) {
            int r = idx >> 3, q = idx & 7;
            int gr = row0 + r;
            uint2 packed = make_uint2(0u, 0u);
            if (gr < NN) {
                float4 v = *(const float4*)(x + (long)gr * 128 + c * 32 + q * 4);
                __half2 p0 = __floats2half2_rn(v.x, v.y);
                __half2 p1 = __floats2half2_rn(v.z, v.w);
                packed.x = *(const uint32_t*)&p0;
                packed.y = *(const uint32_t*)&p1;
            }
            *(uint2*)(hs2 + r * 20 + q * 2) = packed;
        }
        __syncthreads();

        const uint32_t* whu = (const uint32_t*)Wh;
        const uint32_t* hsu = (const uint32_t*)hs2;
#pragma unroll
        for (int ks = 0; ks < 2; ks++) {
            const int kb = ks * 8;
            uint32_t a[2][4];
#pragma unroll
            for (int s = 0; s < 2; s++) {
                const int rb = wm * 32 + s * 16;
                a[s][0] = hsu[(rb + gid) * 20 + kb + tig];
                a[s][1] = hsu[(rb + gid + 8) * 20 + kb + tig];
                a[s][2] = hsu[(rb + gid) * 20 + kb + tig + 4];
                a[s][3] = hsu[(rb + gid + 8) * 20 + kb + tig + 4];
            }
#pragma unroll
            for (int t = 0; t < NT; t++) {
                int n = wn * (D / 4) + t * 8 + gid;
                uint32_t b0 = whu[n * 20 + kb + tig];
                uint32_t b1 = whu[n * 20 + kb + tig + 4];
                mma_f16(acc[0][t], a[0][0], a[0][1], a[0][2], a[0][3], b0, b1);
                mma_f16(acc[1][t], a[1][0], a[1][1], a[1][2], a[1][3], b0, b1);
            }
        }
        __syncthreads();
    }

#pragma unroll
    for (int s = 0; s < 2; s++) {
        const int r0 = row0 + wm * 32 + s * 16 + gid;
        const int r1 = r0 + 8;
#pragma unroll
        for (int t = 0; t < NT; t++) {
            int cidx = wn * (D / 8) + t * 4 + tig;
            if (r0 < NN) g_mA[(long)r0 * 64 + cidx] = __floats2half2_rn(acc[s][t].x, acc[s][t].y);
            if (r1 < NN) g_mA[(long)r1 * 64 + cidx] = __floats2half2_rn(acc[s][t].z, acc[s][t].w);
        }
    }
}

__global__ __launch_bounds__(256) void k_fill_gemm1(const void* __restrict__ ei,
                                                    const float* __restrict__ ew,
                                                    const float* __restrict__ x,
                                                    const float* __restrict__ W) {
    if (blockIdx.x < EB) fill_body(ei, ew);
    else                 gemm1_body(x, W);
}

// ---------------------------------------------------------------------------
// Fused gather+GEMM layer (proven R13), gather loop 2-way unrolled for MLP.
// ---------------------------------------------------------------------------
template <int D, bool A_TO_B>
__global__ __launch_bounds__(256) void k_fused(const float* __restrict__ bprev,
                                               const float* __restrict__ W) {
    constexpr int NT = D / 32;
    constexpr int HS = 68;
    __shared__ __half2 Wh[D * 20];
    __shared__ __half2 hs2[64 * HS];

    const __half2* min_ = A_TO_B ? g_mA : g_mB;
    __half2*       mout = A_TO_B ? g_mB : g_mA;

    const int tid = threadIdx.x;
    const int warp = tid >> 5, lane = tid & 31;
    const int row0 = blockIdx.x * 64;

    // ---- gather phase ----
    {
        const uint2* mh = (const uint2*)min_;
        float bx = __ldg(bprev + lane * 4 + 0);
        float by = __ldg(bprev + lane * 4 + 1);
        float bz = __ldg(bprev + lane * 4 + 2);
        float bw = __ldg(bprev + lane * 4 + 3);
#pragma unroll
        for (int j = 0; j < 8; j++) {
            int r = warp * 8 + j;
            int n = row0 + r;
            uint2 packed = make_uint2(0u, 0u);
            if (n < NN) {
                int beg = g_off[n], end = g_off[n + 1];
                float dn = g_dinv[n];
                float sl = dn * dn;
                float4 acc;
                {
                    uint2 raw = mh[(long)n * 32 + lane];
                    float2 a0 = __half22float2(*(const __half2*)&raw.x);
                    float2 a1 = __half22float2(*(const __half2*)&raw.y);
                    acc = make_float4(a0.x * sl, a0.y * sl, a1.x * sl, a1.y * sl);
                }
                int i = beg;
                for (; i + 1 < end; i += 2) {  // 2-way unroll: 2x MLP
                    uint2 e0 = g_edge[i];
                    uint2 e1 = g_edge[i + 1];
                    uint2 r0 = mh[(long)e0.x * 32 + lane];
                    uint2 r1 = mh[(long)e1.x * 32 + lane];
                    float c0 = __uint_as_float(e0.y);
                    float c1 = __uint_as_float(e1.y);
                    float2 v0 = __half22float2(*(const __half2*)&r0.x);
                    float2 v1 = __half22float2(*(const __half2*)&r0.y);
                    float2 u0 = __half22float2(*(const __half2*)&r1.x);
                    float2 u1 = __half22float2(*(const __half2*)&r1.y);
                    acc.x += c0 * v0.x + c1 * u0.x;
                    acc.y += c0 * v0.y + c1 * u0.y;
                    acc.z += c0 * v1.x + c1 * u1.x;
                    acc.w += c0 * v1.y + c1 * u1.y;
                }
                if (i < end) {
                    uint2 er = g_edge[i];
                    float cf = __uint_as_float(er.y);
                    uint2 raw = mh[(long)er.x * 32 + lane];
                    float2 v0 = __half22float2(*(const __half2*)&raw.x);
                    float2 v1 = __half22float2(*(const __half2*)&raw.y);
                    acc.x += cf * v0.x; acc.y += cf * v0.y;
                    acc.z += cf * v1.x; acc.w += cf * v1.y;
                }
                acc.x = fmaxf(acc.x + bx, 0.0f);
                acc.y = fmaxf(acc.y + by, 0.0f);
                acc.z = fmaxf(acc.z + bz, 0.0f);
                acc.w = fmaxf(acc.w + bw, 0.0f);
                __half2 p0 = __floats2half2_rn(acc.x, acc.y);
                __half2 p1 = __floats2half2_rn(acc.z, acc.w);
                packed.x = *(const uint32_t*)&p0;
                packed.y = *(const uint32_t*)&p1;
            }
            *(uint2*)(hs2 + r * HS + lane * 2) = packed;
        }
    }
    __syncthreads();

    // ---- GEMM phase ----
    const int wm = warp >> 2, wn = warp & 3;
    const int gid = lane >> 2, tig = lane & 3;

    float4 acc[2][NT];
#pragma unroll
    for (int s = 0; s < 2; s++)
#pragma unroll
        for (int t = 0; t < NT; t++) acc[s][t] = make_float4(0.f, 0.f, 0.f, 0.f);

    const uint32_t* hsu = (const uint32_t*)hs2;
    for (int c = 0; c < 4; c++) {
        for (int idx = tid; idx < D * 16; idx += 256) {
            int n = idx >> 4, kk = idx & 15;
            float2 wv = *(const float2*)(W + n * 128 + c * 32 + kk * 2);
            Wh[n * 20 + kk] = __floats2half2_rn(wv.x, wv.y);
        }
        __syncthreads();

        const uint32_t* whu = (const uint32_t*)Wh;
#pragma unroll
        for (int ks = 0; ks < 2; ks++) {
            const int kb = c * 16 + ks * 8;
            uint32_t a[2][4];
#pragma unroll
            for (int s = 0; s < 2; s++) {
                const int rb = wm * 32 + s * 16;
                a[s][0] = hsu[(rb + gid) * HS + kb + tig];
                a[s][1] = hsu[(rb + gid + 8) * HS + kb + tig];
                a[s][2] = hsu[(rb + gid) * HS + kb + tig + 4];
                a[s][3] = hsu[(rb + gid + 8) * HS + kb + tig + 4];
            }
#pragma unroll
            for (int t = 0; t < NT; t++) {
                int n = wn * (D / 4) + t * 8 + gid;
                uint32_t b0 = whu[n * 20 + ks * 8 + tig];
                uint32_t b1 = whu[n * 20 + ks * 8 + tig + 4];
                mma_f16(acc[0][t], a[0][0], a[0][1], a[0][2], a[0][3], b0, b1);
                mma_f16(acc[1][t], a[1][0], a[1][1], a[1][2], a[1][3], b0, b1);
            }
        }
        __syncthreads();
    }

#pragma unroll
    for (int s = 0; s < 2; s++) {
        const int r0 = row0 + wm * 32 + s * 16 + gid;
        const int r1 = r0 + 8;
#pragma unroll
        for (int t = 0; t < NT; t++) {
            int cidx = wn * (D / 8) + t * 4 + tig;
            if (r0 < NN) mout[(long)r0 * (D / 2) + cidx] = __floats2half2_rn(acc[s][t].x, acc[s][t].y);
            if (r1 < NN) mout[(long)r1 * (D / 2) + cidx] = __floats2half2_rn(acc[s][t].z, acc[s][t].w);
        }
    }
}

// ---------------------------------------------------------------------------
// Final gather: g_mA (fp16, 64 cols) -> fp32 out; 2-way unrolled.
// ---------------------------------------------------------------------------
__global__ __launch_bounds__(256) void k_gather_out(const float* __restrict__ b,
                                                    float* __restrict__ outp) {
    int gw = (blockIdx.x * blockDim.x + threadIdx.x) >> 5;
    int lane = threadIdx.x & 31;
    int n = gw * 2 + (lane >> 4);
    int l = lane & 15;
    if (n >= NN) return;
    const uint2* mh = (const uint2*)g_mA;
    int beg = g_off[n], end = g_off[n + 1];
    float dn = g_dinv[n];
    float sl = dn * dn;
    float4 acc;
    {
        uint2 raw = mh[(long)n * 16 + l];
        float2 a0 = __half22float2(*(const __half2*)&raw.x);
        float2 a1 = __half22float2(*(const __half2*)&raw.y);
        acc = make_float4(a0.x * sl, a0.y * sl, a1.x * sl, a1.y * sl);
    }
    int i = beg;
    for (; i + 1 < end; i += 2) {
        uint2 e0 = g_edge[i];
        uint2 e1 = g_edge[i + 1];
        uint2 r0 = mh[(long)e0.x * 16 + l];
        uint2 r1 = mh[(long)e1.x * 16 + l];
        float c0 = __uint_as_float(e0.y);
        float c1 = __uint_as_float(e1.y);
        float2 v0 = __half22float2(*(const __half2*)&r0.x);
        float2 v1 = __half22float2(*(const __half2*)&r0.y);
        float2 u0 = __half22float2(*(const __half2*)&r1.x);
        float2 u1 = __half22float2(*(const __half2*)&r1.y);
        acc.x += c0 * v0.x + c1 * u0.x;
        acc.y += c0 * v0.y + c1 * u0.y;
        acc.z += c0 * v1.x + c1 * u1.x;
        acc.w += c0 * v1.y + c1 * u1.y;
    }
    if (i < end) {
        uint2 er = g_edge[i];
        float cf = __uint_as_float(er.y);
        uint2 raw = mh[(long)er.x * 16 + l];
        float2 v0 = __half22float2(*(const __half2*)&raw.x);
        float2 v1 = __half22float2(*(const __half2*)&raw.y);
        acc.x += cf * v0.x; acc.y += cf * v0.y;
        acc.z += cf * v1.x; acc.w += cf * v1.y;
    }
    int j = l * 4;
    acc.x = fmaxf(acc.x + __ldg(b + j + 0), 0.0f);
    acc.y = fmaxf(acc.y + __ldg(b + j + 1), 0.0f);
    acc.z = fmaxf(acc.z + __ldg(b + j + 2), 0.0f);
    acc.w = fmaxf(acc.w + __ldg(b + j + 3), 0.0f);
    ((float4*)outp)[n * 16 + l] = acc;
}

// ---------------------------------------------------------------------------
extern "C" void kernel_launch(void* const* d_in, const int* in_sizes, int n_in,
                              void* d_out, int out_size) {
    const float* x = (const float*)d_in[0];
    const void*  ei = d_in[1];
    const float* ew = (const float*)d_in[2];
    const float* W1 = (const float*)d_in[3];
    const float* b1 = (const float*)d_in[4];
    const float* W2 = (const float*)d_in[5];
    const float* b2 = (const float*)d_in[6];
    const float* W3 = (const float*)d_in[7];
    const float* b3 = (const float*)d_in[8];
    float* out = (float*)d_out;

    const int nB = (NN + 255) / 256;
    const int gemm_blocks = (NN + 63) / 64;           // 782
    const int gout_blocks = (NN * 16 + 255) / 256;    // 3125

    k_deg_count<<<EB, 256>>>(ei, ew);
    k_scan1<<<SCAN_NB, SCAN_B>>>();
    k_scan23<<<nB, 256>>>();
    k_fill_gemm1<<<EB + gemm_blocks, 256>>>(ei, ew, x, W1);   // fill ∥ gemm1
    k_fused<128, true><<<gemm_blocks, 256>>>(b1, W2);         // agg(mA)+b1 @ W2 -> mB
    k_fused<64, false><<<gemm_blocks, 256>>>(b2, W3);         // agg(mB)+b2 @ W3 -> mA
    k_gather_out<<<gout_blocks, 256>>>(b3, out);              // agg(mA)+b3 -> out
}

// round 15
// speedup vs baseline: 1.1511x; 1.1511x over previous
#include <cuda_runtime.h>
#include <cuda_fp16.h>
#include <cstdint>

#define NN 50000
#define NE 800000
#define SCAN_B 512
#define SCAN_NB ((NN + SCAN_B - 1) / SCAN_B)  // 98

// ---------------------------------------------------------------------------
// Scratch (__device__ globals). g_degcnt zero at load, restored by k_scan1.
// Symbols referenced ONLY from device code (R12 lesson).
// ---------------------------------------------------------------------------
__device__ unsigned long long g_degcnt[NN];
__device__ float              g_dinv[NN];
__device__ int                g_off[NN + 1];
__device__ int                g_cursor[NN];
__device__ int                g_bsum[SCAN_NB];
__device__ __align__(8) uint2 g_edge[NE];        // (src, coef bits), sorted by dest
__device__ __align__(16) __half2 g_mA[NN * 64];  // message ping
__device__ __align__(16) __half2 g_mB[NN * 64];  // message pong

// ---------------------------------------------------------------------------
__device__ __forceinline__ void mma_f16(float4& d, uint32_t a0, uint32_t a1,
                                        uint32_t a2, uint32_t a3,
                                        uint32_t b0, uint32_t b1) {
    asm volatile(
        "mma.sync.aligned.m16n8k16.row.col.f32.f16.f16.f32 "
        "{%0,%1,%2,%3}, {%4,%5,%6,%7}, {%8,%9}, {%0,%1,%2,%3};"
        : "+f"(d.x), "+f"(d.y), "+f"(d.z), "+f"(d.w)
        : "r"(a0), "r"(a1), "r"(a2), "r"(a3), "r"(b0), "r"(b1));
}

__device__ __forceinline__ int detect_is64(const int* __restrict__ ei32) {
    __shared__ int nz;
    if (threadIdx.x == 0) nz = 0;
    __syncthreads();
    for (int k = threadIdx.x; k < 512; k += blockDim.x)
        if (ei32[2 * k + 1] != 0) nz = 1;
    __syncthreads();
    return nz == 0;
}

__device__ __forceinline__ int load_idx(const void* ei, long i, int is64) {
    int v = is64 ? (int)((const long long*)ei)[i] : ((const int*)ei)[i];
    return min(max(v, 0), NN - 1);
}

// ---------------------------------------------------------------------------
// Preprocess
// ---------------------------------------------------------------------------
__global__ void k_deg_count(const void* __restrict__ ei, const float* __restrict__ ew) {
    int is64 = detect_is64((const int*)ei);
    int e = blockIdx.x * blockDim.x + threadIdx.x;
    if (e < NE) {
        int col = load_idx(ei, (long)NE + e, is64);
        unsigned long long v =
            (1ull << 40) | (unsigned long long)(ew[e] * 4294967296.0f);
        atomicAdd(&g_degcnt[col], v);
    }
}

__global__ void k_scan1() {
    __shared__ int s[SCAN_B];
    int tid = threadIdx.x;
    int i = blockIdx.x * SCAN_B + tid;
    int v = 0;
    if (i < NN) {
        unsigned long long dc = g_degcnt[i];
        g_degcnt[i] = 0ull;  // restore invariant
        float deg = (float)(dc & 0xFFFFFFFFFFull) * 2.3283064365386963e-10f;
        g_dinv[i] = rsqrtf(deg + 1.0f);
        v = (int)(dc >> 40);
    }
    s[tid] = v;
    __syncthreads();
#pragma unroll
    for (int off = 1; off < SCAN_B; off <<= 1) {
        int t = (tid >= off) ? s[tid - off] : 0;
        __syncthreads();
        s[tid] += t;
        __syncthreads();
    }
    if (i < NN) g_off[i] = s[tid] - v;
    if (tid == SCAN_B - 1) g_bsum[blockIdx.x] = s[tid];
}

__global__ void k_scan23() {
    __shared__ int s[128];
    __shared__ int pre[SCAN_NB];
    int tid = threadIdx.x;
    int v = 0;
    if (tid < 128) { v = (tid < SCAN_NB) ? g_bsum[tid] : 0; s[tid] = v; }
    __syncthreads();
#pragma unroll
    for (int off = 1; off < 128; off <<= 1) {
        int t = 0;
        if (tid < 128 && tid >= off) t = s[tid - off];
        __syncthreads();
        if (tid < 128) s[tid] += t;
        __syncthreads();
    }
    if (tid < SCAN_NB) pre[tid] = s[tid] - v;
    __syncthreads();
    int i = blockIdx.x * blockDim.x + tid;
    if (i < NN) {
        int o = g_off[i] + pre[i / SCAN_B];
        g_off[i] = o;
        g_cursor[i] = o;
    }
    if (i == 0) g_off[NN] = NE;
}

__global__ void k_fill(const void* __restrict__ ei, const float* __restrict__ ew) {
    int is64 = detect_is64((const int*)ei);
    int e = blockIdx.x * blockDim.x + threadIdx.x;
    if (e < NE) {
        int row = load_idx(ei, e, is64);
        int col = load_idx(ei, (long)NE + e, is64);
        int pos = atomicAdd(&g_cursor[col], 1);
        pos = min(max(pos, 0), NE - 1);
        float coef = g_dinv[row] * ew[e] * g_dinv[col];
        uint2 rec;
        rec.x = (uint32_t)row;
        rec.y = __float_as_uint(coef);
        g_edge[pos] = rec;
    }
}

// ---------------------------------------------------------------------------
// Layer-1 GEMM (x fp32 -> mA fp16): m = x @ W1^T. Proven R11/R13 structure.
// ---------------------------------------------------------------------------
__global__ __launch_bounds__(256) void k_gemm1(const float* __restrict__ x,
                                               const float* __restrict__ W) {
    constexpr int D = 128, NT = D / 32;
    __shared__ __half2 Wh[D * 20];
    __shared__ __half2 hs2[64 * 20];

    const int tid = threadIdx.x;
    const int warp = tid >> 5, lane = tid & 31;
    const int wm = warp >> 2, wn = warp & 3;
    const int gid = lane >> 2, tig = lane & 3;
    const int row0 = blockIdx.x * 64;

    float4 acc[2][NT];
#pragma unroll
    for (int s = 0; s < 2; s++)
#pragma unroll
        for (int t = 0; t < NT; t++) acc[s][t] = make_float4(0.f, 0.f, 0.f, 0.f);

    for (int c = 0; c < 4; c++) {
        for (int idx = tid; idx < D * 16; idx += 256) {
            int n = idx >> 4, kk = idx & 15;
            float2 wv = *(const float2*)(W + n * 128 + c * 32 + kk * 2);
            Wh[n * 20 + kk] = __floats2half2_rn(wv.x, wv.y);
        }
        for (int idx = tid; idx < 512; idx += 256) {
            int r = idx >> 3, q = idx & 7;
            int gr = row0 + r;
            uint2 packed = make_uint2(0u, 0u);
            if (gr < NN) {
                float4 v = *(const float4*)(x + (long)gr * 128 + c * 32 + q * 4);
                __half2 p0 = __floats2half2_rn(v.x, v.y);
                __half2 p1 = __floats2half2_rn(v.z, v.w);
                packed.x = *(const uint32_t*)&p0;
                packed.y = *(const uint32_t*)&p1;
            }
            *(uint2*)(hs2 + r * 20 + q * 2) = packed;
        }
        __syncthreads();

        const uint32_t* whu = (const uint32_t*)Wh;
        const uint32_t* hsu = (const uint32_t*)hs2;
#pragma unroll
        for (int ks = 0; ks < 2; ks++) {
            const int kb = ks * 8;
            uint32_t a[2][4];
#pragma unroll
            for (int s = 0; s < 2; s++) {
                const int rb = wm * 32 + s * 16;
                a[s][0] = hsu[(rb + gid) * 20 + kb + tig];
                a[s][1] = hsu[(rb + gid + 8) * 20 + kb + tig];
                a[s][2] = hsu[(rb + gid) * 20 + kb + tig + 4];
                a[s][3] = hsu[(rb + gid + 8) * 20 + kb + tig + 4];
            }
#pragma unroll
            for (int t = 0; t < NT; t++) {
                int n = wn * (D / 4) + t * 8 + gid;
                uint32_t b0 = whu[n * 20 + kb + tig];
                uint32_t b1 = whu[n * 20 + kb + tig + 4];
                mma_f16(acc[0][t], a[0][0], a[0][1], a[0][2], a[0][3], b0, b1);
                mma_f16(acc[1][t], a[1][0], a[1][1], a[1][2], a[1][3], b0, b1);
            }
        }
        __syncthreads();
    }

#pragma unroll
    for (int s = 0; s < 2; s++) {
        const int r0 = row0 + wm * 32 + s * 16 + gid;
        const int r1 = r0 + 8;
#pragma unroll
        for (int t = 0; t < NT; t++) {
            int cidx = wn * (D / 8) + t * 4 + tig;
            if (r0 < NN) g_mA[(long)r0 * 64 + cidx] = __floats2half2_rn(acc[s][t].x, acc[s][t].y);
            if (r1 < NN) g_mA[(long)r1 * 64 + cidx] = __floats2half2_rn(acc[s][t].z, acc[s][t].w);
        }
    }
}

// ---------------------------------------------------------------------------
// Fused gather+GEMM layer — exact R13 version (no unroll; proven 145.9).
// ---------------------------------------------------------------------------
template <int D, bool A_TO_B>
__global__ __launch_bounds__(256) void k_fused(const float* __restrict__ bprev,
                                               const float* __restrict__ W) {
    constexpr int NT = D / 32;
    constexpr int HS = 68;
    __shared__ __half2 Wh[D * 20];
    __shared__ __half2 hs2[64 * HS];

    const __half2* min_ = A_TO_B ? g_mA : g_mB;
    __half2*       mout = A_TO_B ? g_mB : g_mA;

    const int tid = threadIdx.x;
    const int warp = tid >> 5, lane = tid & 31;
    const int row0 = blockIdx.x * 64;

    // ---- gather phase ----
    {
        const uint2* mh = (const uint2*)min_;
        float bx = __ldg(bprev + lane * 4 + 0);
        float by = __ldg(bprev + lane * 4 + 1);
        float bz = __ldg(bprev + lane * 4 + 2);
        float bw = __ldg(bprev + lane * 4 + 3);
#pragma unroll
        for (int j = 0; j < 8; j++) {
            int r = warp * 8 + j;
            int n = row0 + r;
            uint2 packed = make_uint2(0u, 0u);
            if (n < NN) {
                int beg = g_off[n], end = g_off[n + 1];
                float dn = g_dinv[n];
                float sl = dn * dn;
                float4 acc;
                {
                    uint2 raw = mh[(long)n * 32 + lane];
                    float2 a0 = __half22float2(*(const __half2*)&raw.x);
                    float2 a1 = __half22float2(*(const __half2*)&raw.y);
                    acc = make_float4(a0.x * sl, a0.y * sl, a1.x * sl, a1.y * sl);
                }
                for (int i = beg; i < end; i++) {
                    uint2 er = g_edge[i];
                    float cf = __uint_as_float(er.y);
                    uint2 raw = mh[(long)er.x * 32 + lane];
                    float2 v0 = __half22float2(*(const __half2*)&raw.x);
                    float2 v1 = __half22float2(*(const __half2*)&raw.y);
                    acc.x += cf * v0.x; acc.y += cf * v0.y;
                    acc.z += cf * v1.x; acc.w += cf * v1.y;
                }
                acc.x = fmaxf(acc.x + bx, 0.0f);
                acc.y = fmaxf(acc.y + by, 0.0f);
                acc.z = fmaxf(acc.z + bz, 0.0f);
                acc.w = fmaxf(acc.w + bw, 0.0f);
                __half2 p0 = __floats2half2_rn(acc.x, acc.y);
                __half2 p1 = __floats2half2_rn(acc.z, acc.w);
                packed.x = *(const uint32_t*)&p0;
                packed.y = *(const uint32_t*)&p1;
            }
            *(uint2*)(hs2 + r * HS + lane * 2) = packed;
        }
    }
    __syncthreads();

    // ---- GEMM phase ----
    const int wm = warp >> 2, wn = warp & 3;
    const int gid = lane >> 2, tig = lane & 3;

    float4 acc[2][NT];
#pragma unroll
    for (int s = 0; s < 2; s++)
#pragma unroll
        for (int t = 0; t < NT; t++) acc[s][t] = make_float4(0.f, 0.f, 0.f, 0.f);

    const uint32_t* hsu = (const uint32_t*)hs2;
    for (int c = 0; c < 4; c++) {
        for (int idx = tid; idx < D * 16; idx += 256) {
            int n = idx >> 4, kk = idx & 15;
            float2 wv = *(const float2*)(W + n * 128 + c * 32 + kk * 2);
            Wh[n * 20 + kk] = __floats2half2_rn(wv.x, wv.y);
        }
        __syncthreads();

        const uint32_t* whu = (const uint32_t*)Wh;
#pragma unroll
        for (int ks = 0; ks < 2; ks++) {
            const int kb = c * 16 + ks * 8;
            uint32_t a[2][4];
#pragma unroll
            for (int s = 0; s < 2; s++) {
                const int rb = wm * 32 + s * 16;
                a[s][0] = hsu[(rb + gid) * HS + kb + tig];
                a[s][1] = hsu[(rb + gid + 8) * HS + kb + tig];
                a[s][2] = hsu[(rb + gid) * HS + kb + tig + 4];
                a[s][3] = hsu[(rb + gid + 8) * HS + kb + tig + 4];
            }
#pragma unroll
            for (int t = 0; t < NT; t++) {
                int n = wn * (D / 4) + t * 8 + gid;
                uint32_t b0 = whu[n * 20 + ks * 8 + tig];
                uint32_t b1 = whu[n * 20 + ks * 8 + tig + 4];
                mma_f16(acc[0][t], a[0][0], a[0][1], a[0][2], a[0][3], b0, b1);
                mma_f16(acc[1][t], a[1][0], a[1][1], a[1][2], a[1][3], b0, b1);
            }
        }
        __syncthreads();
    }

#pragma unroll
    for (int s = 0; s < 2; s++) {
        const int r0 = row0 + wm * 32 + s * 16 + gid;
        const int r1 = r0 + 8;
#pragma unroll
        for (int t = 0; t < NT; t++) {
            int cidx = wn * (D / 8) + t * 4 + tig;
            if (r0 < NN) mout[(long)r0 * (D / 2) + cidx] = __floats2half2_rn(acc[s][t].x, acc[s][t].y);
            if (r1 < NN) mout[(long)r1 * (D / 2) + cidx] = __floats2half2_rn(acc[s][t].z, acc[s][t].w);
        }
    }
}

// ---------------------------------------------------------------------------
// Final gather: g_mA (fp16, 64 cols) -> fp32 out; 2-way unrolled (the ONLY
// change vs R13 — isolated MLP experiment in a standalone latency-bound kernel).
// ---------------------------------------------------------------------------
__global__ __launch_bounds__(256) void k_gather_out(const float* __restrict__ b,
                                                    float* __restrict__ outp) {
    int gw = (blockIdx.x * blockDim.x + threadIdx.x) >> 5;
    int lane = threadIdx.x & 31;
    int n = gw * 2 + (lane >> 4);
    int l = lane & 15;
    if (n >= NN) return;
    const uint2* mh = (const uint2*)g_mA;
    int beg = g_off[n], end = g_off[n + 1];
    float dn = g_dinv[n];
    float sl = dn * dn;
    float4 acc;
    {
        uint2 raw = mh[(long)n * 16 + l];
        float2 a0 = __half22float2(*(const __half2*)&raw.x);
        float2 a1 = __half22float2(*(const __half2*)&raw.y);
        acc = make_float4(a0.x * sl, a0.y * sl, a1.x * sl, a1.y * sl);
    }
    int i = beg;
    for (; i + 1 < end; i += 2) {  // 2-way unroll: 2x edge-record MLP
        uint2 e0 = g_edge[i];
        uint2 e1 = g_edge[i + 1];
        uint2 r0 = mh[(long)e0.x * 16 + l];
        uint2 r1 = mh[(long)e1.x * 16 + l];
        float c0 = __uint_as_float(e0.y);
        float c1 = __uint_as_float(e1.y);
        float2 v0 = __half22float2(*(const __half2*)&r0.x);
        float2 v1 = __half22float2(*(const __half2*)&r0.y);
        float2 u0 = __half22float2(*(const __half2*)&r1.x);
        float2 u1 = __half22float2(*(const __half2*)&r1.y);
        acc.x += c0 * v0.x + c1 * u0.x;
        acc.y += c0 * v0.y + c1 * u0.y;
        acc.z += c0 * v1.x + c1 * u1.x;
        acc.w += c0 * v1.y + c1 * u1.y;
    }
    if (i < end) {
        uint2 er = g_edge[i];
        float cf = __uint_as_float(er.y);
        uint2 raw = mh[(long)er.x * 16 + l];
        float2 v0 = __half22float2(*(const __half2*)&raw.x);
        float2 v1 = __half22float2(*(const __half2*)&raw.y);
        acc.x += cf * v0.x; acc.y += cf * v0.y;
        acc.z += cf * v1.x; acc.w += cf * v1.y;
    }
    int j = l * 4;
    acc.x = fmaxf(acc.x + __ldg(b + j + 0), 0.0f);
    acc.y = fmaxf(acc.y + __ldg(b + j + 1), 0.0f);
    acc.z = fmaxf(acc.z + __ldg(b + j + 2), 0.0f);
    acc.w = fmaxf(acc.w + __ldg(b + j + 3), 0.0f);
    ((float4*)outp)[n * 16 + l] = acc;
}

// ---------------------------------------------------------------------------
extern "C" void kernel_launch(void* const* d_in, const int* in_sizes, int n_in,
                              void* d_out, int out_size) {
    const float* x = (const float*)d_in[0];
    const void*  ei = d_in[1];
    const float* ew = (const float*)d_in[2];
    const float* W1 = (const float*)d_in[3];
    const float* b1 = (const float*)d_in[4];
    const float* W2 = (const float*)d_in[5];
    const float* b2 = (const float*)d_in[6];
    const float* W3 = (const float*)d_in[7];
    const float* b3 = (const float*)d_in[8];
    float* out = (float*)d_out;

    const int eB = (NE + 255) / 256;
    const int nB = (NN + 255) / 256;
    const int gemm_blocks = (NN + 63) / 64;           // 782
    const int gout_blocks = (NN * 16 + 255) / 256;    // 3125

    // --- preprocess: deg/cnt -> scan -> CSR fill ---
    k_deg_count<<<eB, 256>>>(ei, ew);
    k_scan1<<<SCAN_NB, SCAN_B>>>();
    k_scan23<<<nB, 256>>>();
    k_fill<<<eB, 256>>>(ei, ew);

    // --- layers: gemm1 -> fused(gather+gemm) x2 -> gather_out ---
    k_gemm1<<<gemm_blocks, 256>>>(x, W1);
    k_fused<128, true><<<gemm_blocks, 256>>>(b1, W2);
    k_fused<64, false><<<gemm_blocks, 256>>>(b2, W3);
    k_gather_out<<<gout_blocks, 256>>>(b3, out);
}

// round 16
// speedup vs baseline: 1.1868x; 1.0310x over previous
#include <cuda_runtime.h>
#include <cuda_fp16.h>
#include <cstdint>

#define NN 50000
#define NE 800000
#define SCAN_B 512
#define SCAN_NB ((NN + SCAN_B - 1) / SCAN_B)  // 98

// ---------------------------------------------------------------------------
// Scratch (__device__ globals). g_degcnt zero at load, restored by k_scan1.
// Symbols referenced ONLY from device code (R12 lesson).
// ---------------------------------------------------------------------------
__device__ unsigned long long g_degcnt[NN];
__device__ float              g_dinv[NN];
__device__ int                g_off[NN + 1];
__device__ int                g_bsum[SCAN_NB];
__device__ int                g_rank[NE];       // within-destination rank of each edge
__device__ __align__(8) uint2 g_edge[NE];       // (src, coef bits), sorted by dest
__device__ __align__(16) __half2 g_mA[NN * 64]; // message ping
__device__ __align__(16) __half2 g_mB[NN * 64]; // message pong

// ---------------------------------------------------------------------------
__device__ __forceinline__ void mma_f16(float4& d, uint32_t a0, uint32_t a1,
                                        uint32_t a2, uint32_t a3,
                                        uint32_t b0, uint32_t b1) {
    asm volatile(
        "mma.sync.aligned.m16n8k16.row.col.f32.f16.f16.f32 "
        "{%0,%1,%2,%3}, {%4,%5,%6,%7}, {%8,%9}, {%0,%1,%2,%3};"
        : "+f"(d.x), "+f"(d.y), "+f"(d.z), "+f"(d.w)
        : "r"(a0), "r"(a1), "r"(a2), "r"(a3), "r"(b0), "r"(b1));
}

__device__ __forceinline__ int detect_is64(const int* __restrict__ ei32) {
    __shared__ int nz;
    if (threadIdx.x == 0) nz = 0;
    __syncthreads();
    for (int k = threadIdx.x; k < 512; k += blockDim.x)
        if (ei32[2 * k + 1] != 0) nz = 1;
    __syncthreads();
    return nz == 0;
}

__device__ __forceinline__ int load_idx(const void* ei, long i, int is64) {
    int v = is64 ? (int)((const long long*)ei)[i] : ((const int*)ei)[i];
    return min(max(v, 0), NN - 1);
}

// ---------------------------------------------------------------------------
// Preprocess. deg_count's packed atomic RETURNS the old value -> bits[40..)
// are this edge's within-destination rank. Recycle it so k_fill needs NO
// atomics at all (pos = off[col] + rank).
// ---------------------------------------------------------------------------
__global__ void k_deg_count(const void* __restrict__ ei, const float* __restrict__ ew) {
    int is64 = detect_is64((const int*)ei);
    int e = blockIdx.x * blockDim.x + threadIdx.x;
    if (e < NE) {
        int col = load_idx(ei, (long)NE + e, is64);
        unsigned long long v =
            (1ull << 40) | (unsigned long long)(ew[e] * 4294967296.0f);
        unsigned long long old = atomicAdd(&g_degcnt[col], v);
        g_rank[e] = (int)(old >> 40);  // coalesced 4B store
    }
}

__global__ void k_scan1() {
    __shared__ int s[SCAN_B];
    int tid = threadIdx.x;
    int i = blockIdx.x * SCAN_B + tid;
    int v = 0;
    if (i < NN) {
        unsigned long long dc = g_degcnt[i];
        g_degcnt[i] = 0ull;  // restore invariant
        float deg = (float)(dc & 0xFFFFFFFFFFull) * 2.3283064365386963e-10f;
        g_dinv[i] = rsqrtf(deg + 1.0f);
        v = (int)(dc >> 40);
    }
    s[tid] = v;
    __syncthreads();
#pragma unroll
    for (int off = 1; off < SCAN_B; off <<= 1) {
        int t = (tid >= off) ? s[tid - off] : 0;
        __syncthreads();
        s[tid] += t;
        __syncthreads();
    }
    if (i < NN) g_off[i] = s[tid] - v;
    if (tid == SCAN_B - 1) g_bsum[blockIdx.x] = s[tid];
}

__global__ void k_scan23() {
    __shared__ int s[128];
    __shared__ int pre[SCAN_NB];
    int tid = threadIdx.x;
    int v = 0;
    if (tid < 128) { v = (tid < SCAN_NB) ? g_bsum[tid] : 0; s[tid] = v; }
    __syncthreads();
#pragma unroll
    for (int off = 1; off < 128; off <<= 1) {
        int t = 0;
        if (tid < 128 && tid >= off) t = s[tid - off];
        __syncthreads();
        if (tid < 128) s[tid] += t;
        __syncthreads();
    }
    if (tid < SCAN_NB) pre[tid] = s[tid] - v;
    __syncthreads();
    int i = blockIdx.x * blockDim.x + tid;
    if (i < NN) g_off[i] = g_off[i] + pre[i / SCAN_B];
    if (i == 0) g_off[NN] = NE;
}

// Atomic-free fill: pure reads + one 8B scattered store per edge.
__global__ void k_fill(const void* __restrict__ ei, const float* __restrict__ ew) {
    int is64 = detect_is64((const int*)ei);
    int e = blockIdx.x * blockDim.x + threadIdx.x;
    if (e < NE) {
        int row = load_idx(ei, e, is64);
        int col = load_idx(ei, (long)NE + e, is64);
        int pos = g_off[col] + g_rank[e];
        pos = min(max(pos, 0), NE - 1);
        float coef = g_dinv[row] * ew[e] * g_dinv[col];
        uint2 rec;
        rec.x = (uint32_t)row;
        rec.y = __float_as_uint(coef);
        g_edge[pos] = rec;
    }
}

// ---------------------------------------------------------------------------
// Layer-1 GEMM (x fp32 -> mA fp16): m = x @ W1^T. Proven R11/R13 structure.
// ---------------------------------------------------------------------------
__global__ __launch_bounds__(256) void k_gemm1(const float* __restrict__ x,
                                               const float* __restrict__ W) {
    constexpr int D = 128, NT = D / 32;
    __shared__ __half2 Wh[D * 20];
    __shared__ __half2 hs2[64 * 20];

    const int tid = threadIdx.x;
    const int warp = tid >> 5, lane = tid & 31;
    const int wm = warp >> 2, wn = warp & 3;
    const int gid = lane >> 2, tig = lane & 3;
    const int row0 = blockIdx.x * 64;

    float4 acc[2][NT];
#pragma unroll
    for (int s = 0; s < 2; s++)
#pragma unroll
        for (int t = 0; t < NT; t++) acc[s][t] = make_float4(0.f, 0.f, 0.f, 0.f);

    for (int c = 0; c < 4; c++) {
        for (int idx = tid; idx < D * 16; idx += 256) {
            int n = idx >> 4, kk = idx & 15;
            float2 wv = *(const float2*)(W + n * 128 + c * 32 + kk * 2);
            Wh[n * 20 + kk] = __floats2half2_rn(wv.x, wv.y);
        }
        for (int idx = tid; idx < 512; idx += 256) {
            int r = idx >> 3, q = idx & 7;
            int gr = row0 + r;
            uint2 packed = make_uint2(0u, 0u);
            if (gr < NN) {
                float4 v = *(const float4*)(x + (long)gr * 128 + c * 32 + q * 4);
                __half2 p0 = __floats2half2_rn(v.x, v.y);
                __half2 p1 = __floats2half2_rn(v.z, v.w);
                packed.x = *(const uint32_t*)&p0;
                packed.y = *(const uint32_t*)&p1;
            }
            *(uint2*)(hs2 + r * 20 + q * 2) = packed;
        }
        __syncthreads();

        const uint32_t* whu = (const uint32_t*)Wh;
        const uint32_t* hsu = (const uint32_t*)hs2;
#pragma unroll
        for (int ks = 0; ks < 2; ks++) {
            const int kb = ks * 8;
            uint32_t a[2][4];
#pragma unroll
            for (int s = 0; s < 2; s++) {
                const int rb = wm * 32 + s * 16;
                a[s][0] = hsu[(rb + gid) * 20 + kb + tig];
                a[s][1] = hsu[(rb + gid + 8) * 20 + kb + tig];
                a[s][2] = hsu[(rb + gid) * 20 + kb + tig + 4];
                a[s][3] = hsu[(rb + gid + 8) * 20 + kb + tig + 4];
            }
#pragma unroll
            for (int t = 0; t < NT; t++) {
                int n = wn * (D / 4) + t * 8 + gid;
                uint32_t b0 = whu[n * 20 + kb + tig];
                uint32_t b1 = whu[n * 20 + kb + tig + 4];
                mma_f16(acc[0][t], a[0][0], a[0][1], a[0][2], a[0][3], b0, b1);
                mma_f16(acc[1][t], a[1][0], a[1][1], a[1][2], a[1][3], b0, b1);
            }
        }
        __syncthreads();
    }

#pragma unroll
    for (int s = 0; s < 2; s++) {
        const int r0 = row0 + wm * 32 + s * 16 + gid;
        const int r1 = r0 + 8;
#pragma unroll
        for (int t = 0; t < NT; t++) {
            int cidx = wn * (D / 8) + t * 4 + tig;
            if (r0 < NN) g_mA[(long)r0 * 64 + cidx] = __floats2half2_rn(acc[s][t].x, acc[s][t].y);
            if (r1 < NN) g_mA[(long)r1 * 64 + cidx] = __floats2half2_rn(acc[s][t].z, acc[s][t].w);
        }
    }
}

// ---------------------------------------------------------------------------
// Fused gather+GEMM layer — exact R13 version (proven 145.9).
// ---------------------------------------------------------------------------
template <int D, bool A_TO_B>
__global__ __launch_bounds__(256) void k_fused(const float* __restrict__ bprev,
                                               const float* __restrict__ W) {
    constexpr int NT = D / 32;
    constexpr int HS = 68;
    __shared__ __half2 Wh[D * 20];
    __shared__ __half2 hs2[64 * HS];

    const __half2* min_ = A_TO_B ? g_mA : g_mB;
    __half2*       mout = A_TO_B ? g_mB : g_mA;

    const int tid = threadIdx.x;
    const int warp = tid >> 5, lane = tid & 31;
    const int row0 = blockIdx.x * 64;

    // ---- gather phase ----
    {
        const uint2* mh = (const uint2*)min_;
        float bx = __ldg(bprev + lane * 4 + 0);
        float by = __ldg(bprev + lane * 4 + 1);
        float bz = __ldg(bprev + lane * 4 + 2);
        float bw = __ldg(bprev + lane * 4 + 3);
#pragma unroll
        for (int j = 0; j < 8; j++) {
            int r = warp * 8 + j;
            int n = row0 + r;
            uint2 packed = make_uint2(0u, 0u);
            if (n < NN) {
                int beg = g_off[n], end = g_off[n + 1];
                float dn = g_dinv[n];
                float sl = dn * dn;
                float4 acc;
                {
                    uint2 raw = mh[(long)n * 32 + lane];
                    float2 a0 = __half22float2(*(const __half2*)&raw.x);
                    float2 a1 = __half22float2(*(const __half2*)&raw.y);
                    acc = make_float4(a0.x * sl, a0.y * sl, a1.x * sl, a1.y * sl);
                }
                for (int i = beg; i < end; i++) {
                    uint2 er = g_edge[i];
                    float cf = __uint_as_float(er.y);
                    uint2 raw = mh[(long)er.x * 32 + lane];
                    float2 v0 = __half22float2(*(const __half2*)&raw.x);
                    float2 v1 = __half22float2(*(const __half2*)&raw.y);
                    acc.x += cf * v0.x; acc.y += cf * v0.y;
                    acc.z += cf * v1.x; acc.w += cf * v1.y;
                }
                acc.x = fmaxf(acc.x + bx, 0.0f);
                acc.y = fmaxf(acc.y + by, 0.0f);
                acc.z = fmaxf(acc.z + bz, 0.0f);
                acc.w = fmaxf(acc.w + bw, 0.0f);
                __half2 p0 = __floats2half2_rn(acc.x, acc.y);
                __half2 p1 = __floats2half2_rn(acc.z, acc.w);
                packed.x = *(const uint32_t*)&p0;
                packed.y = *(const uint32_t*)&p1;
            }
            *(uint2*)(hs2 + r * HS + lane * 2) = packed;
        }
    }
    __syncthreads();

    // ---- GEMM phase ----
    const int wm = warp >> 2, wn = warp & 3;
    const int gid = lane >> 2, tig = lane & 3;

    float4 acc[2][NT];
#pragma unroll
    for (int s = 0; s < 2; s++)
#pragma unroll
        for (int t = 0; t < NT; t++) acc[s][t] = make_float4(0.f, 0.f, 0.f, 0.f);

    const uint32_t* hsu = (const uint32_t*)hs2;
    for (int c = 0; c < 4; c++) {
        for (int idx = tid; idx < D * 16; idx += 256) {
            int n = idx >> 4, kk = idx & 15;
            float2 wv = *(const float2*)(W + n * 128 + c * 32 + kk * 2);
            Wh[n * 20 + kk] = __floats2half2_rn(wv.x, wv.y);
        }
        __syncthreads();

        const uint32_t* whu = (const uint32_t*)Wh;
#pragma unroll
        for (int ks = 0; ks < 2; ks++) {
            const int kb = c * 16 + ks * 8;
            uint32_t a[2][4];
#pragma unroll
            for (int s = 0; s < 2; s++) {
                const int rb = wm * 32 + s * 16;
                a[s][0] = hsu[(rb + gid) * HS + kb + tig];
                a[s][1] = hsu[(rb + gid + 8) * HS + kb + tig];
                a[s][2] = hsu[(rb + gid) * HS + kb + tig + 4];
                a[s][3] = hsu[(rb + gid + 8) * HS + kb + tig + 4];
            }
#pragma unroll
            for (int t = 0; t < NT; t++) {
                int n = wn * (D / 4) + t * 8 + gid;
                uint32_t b0 = whu[n * 20 + ks * 8 + tig];
                uint32_t b1 = whu[n * 20 + ks * 8 + tig + 4];
                mma_f16(acc[0][t], a[0][0], a[0][1], a[0][2], a[0][3], b0, b1);
                mma_f16(acc[1][t], a[1][0], a[1][1], a[1][2], a[1][3], b0, b1);
            }
        }
        __syncthreads();
    }

#pragma unroll
    for (int s = 0; s < 2; s++) {
        const int r0 = row0 + wm * 32 + s * 16 + gid;
        const int r1 = r0 + 8;
#pragma unroll
        for (int t = 0; t < NT; t++) {
            int cidx = wn * (D / 8) + t * 4 + tig;
            if (r0 < NN) mout[(long)r0 * (D / 2) + cidx] = __floats2half2_rn(acc[s][t].x, acc[s][t].y);
            if (r1 < NN) mout[(long)r1 * (D / 2) + cidx] = __floats2half2_rn(acc[s][t].z, acc[s][t].w);
        }
    }
}

// ---------------------------------------------------------------------------
// Final gather — exact R13 version (no unroll; the unroll was a measured
// regression: gathers are L2-throughput-bound, not latency-bound).
// ---------------------------------------------------------------------------
__global__ __launch_bounds__(256) void k_gather_out(const float* __restrict__ b,
                                                    float* __restrict__ outp) {
    int gw = (blockIdx.x * blockDim.x + threadIdx.x) >> 5;
    int lane = threadIdx.x & 31;
    int n = gw * 2 + (lane >> 4);
    int l = lane & 15;
    if (n >= NN) return;
    const uint2* mh = (const uint2*)g_mA;
    int beg = g_off[n], end = g_off[n + 1];
    float dn = g_dinv[n];
    float sl = dn * dn;
    float4 acc;
    {
        uint2 raw = mh[(long)n * 16 + l];
        float2 a0 = __half22float2(*(const __half2*)&raw.x);
        float2 a1 = __half22float2(*(const __half2*)&raw.y);
        acc = make_float4(a0.x * sl, a0.y * sl, a1.x * sl, a1.y * sl);
    }
#pragma unroll 4
    for (int i = beg; i < end; i++) {
        uint2 er = g_edge[i];
        float cf = __uint_as_float(er.y);
        uint2 raw = mh[(long)er.x * 16 + l];
        float2 v0 = __half22float2(*(const __half2*)&raw.x);
        float2 v1 = __half22float2(*(const __half2*)&raw.y);
        acc.x += cf * v0.x; acc.y += cf * v0.y;
        acc.z += cf * v1.x; acc.w += cf * v1.y;
    }
    int j = l * 4;
    acc.x = fmaxf(acc.x + __ldg(b + j + 0), 0.0f);
    acc.y = fmaxf(acc.y + __ldg(b + j + 1), 0.0f);
    acc.z = fmaxf(acc.z + __ldg(b + j + 2), 0.0f);
    acc.w = fmaxf(acc.w + __ldg(b + j + 3), 0.0f);
    ((float4*)outp)[n * 16 + l] = acc;
}

// ---------------------------------------------------------------------------
extern "C" void kernel_launch(void* const* d_in, const int* in_sizes, int n_in,
                              void* d_out, int out_size) {
    const float* x = (const float*)d_in[0];
    const void*  ei = d_in[1];
    const float* ew = (const float*)d_in[2];
    const float* W1 = (const float*)d_in[3];
    const float* b1 = (const float*)d_in[4];
    const float* W2 = (const float*)d_in[5];
    const float* b2 = (const float*)d_in[6];
    const float* W3 = (const float*)d_in[7];
    const float* b3 = (const float*)d_in[8];
    float* out = (float*)d_out;

    const int eB = (NE + 255) / 256;
    const int nB = (NN + 255) / 256;
    const int gemm_blocks = (NN + 63) / 64;           // 782
    const int gout_blocks = (NN * 16 + 255) / 256;    // 3125

    // --- preprocess: deg/cnt(+rank) -> scan -> atomic-free CSR fill ---
    k_deg_count<<<eB, 256>>>(ei, ew);
    k_scan1<<<SCAN_NB, SCAN_B>>>();
    k_scan23<<<nB, 256>>>();
    k_fill<<<eB, 256>>>(ei, ew);

    // --- layers: gemm1 -> fused(gather+gemm) x2 -> gather_out ---
    k_gemm1<<<gemm_blocks, 256>>>(x, W1);
    k_fused<128, true><<<gemm_blocks, 256>>>(b1, W2);
    k_fused<64, false><<<gemm_blocks, 256>>>(b2, W3);
    k_gather_out<<<gout_blocks, 256>>>(b3, out);
}